// round 6
// baseline (speedup 1.0000x reference)
#include <cuda_runtime.h>
#include <cstdint>
#include <cmath>
#include <cstring>
#include <complex>
#include <cstdlib>

#define NTHREADS 256
#define CG_CAP 128

// ---- smem byte offsets ----
#define OFF_CG     0            // float2[128] = 1024
#define OFF_X1     1024         // 5*65*4 = 1300
#define OFF_STRIP  2432         // 160*65*4 = 41600
#define OFF_W      44032        // 32*(M3+8)*4 <= 17408
#define OFF_A      61440        // L3*64*36*4 <= 46080
#define SMEM_TOTAL 107520

struct PathP {
    int m1, m2, L1, L2, off1, off2, woff, m2shift;
    int cg_beg[6];
};
struct Params {
    int npaths, ncg;
    float coeff;
    PathP path[4];
    int   cg_pack[CG_CAP];   // (i*260) | (j*260 << 16)  : pre-scaled byte offsets
    float cg_val[CG_CAP];
};
struct AllParams { Params p[3]; };

// ------------------------------ device helpers ------------------------------

__device__ __forceinline__ uint32_t to_tf32(float f) {
    uint32_t r;
    asm("cvt.rna.tf32.f32 %0, %1;" : "=r"(r) : "f"(f));
    return r;
}

__device__ __forceinline__ void mma8(float* d, const uint32_t* a, const uint32_t* b) {
    asm volatile(
        "mma.sync.aligned.m16n8k8.row.col.f32.tf32.tf32.f32 "
        "{%0,%1,%2,%3}, {%4,%5,%6,%7}, {%8,%9}, {%0,%1,%2,%3};"
        : "+f"(d[0]), "+f"(d[1]), "+f"(d[2]), "+f"(d[3])
        : "r"(a[0]), "r"(a[1]), "r"(a[2]), "r"(a[3]), "r"(b[0]), "r"(b[1]));
}

// ------------------------------ main kernel ---------------------------------

template<int M3, int L3, int OFF3>
__device__ void run_i3(const float* __restrict__ x1, const float* __restrict__ x2,
                       const float* __restrict__ wgt, float* __restrict__ out,
                       const Params& P, int tile)
{
    extern __shared__ char sm[];
    float2*   scg   = (float2*)(sm + OFF_CG);
    float*    x1row = (float*)(sm + OFF_X1);      // [L1][65]
    float*    strip = (float*)(sm + OFF_STRIP);   // [32*L2][65]
    uint32_t* sW    = (uint32_t*)(sm + OFF_W);    // [32][M3+8]
    uint32_t* sA    = (uint32_t*)(sm + OFF_A);    // [L3][64][36]

    const int tid = threadIdx.x, wid = tid >> 5, lane = tid & 31;
    const int cgp = wid & 3, rh = wid >> 2;       // col group, row half
    const int gID = lane >> 2, tIG = lane & 3;
    constexpr int CPW  = M3 / 4;                  // cols per warp per k
    constexpr int NC   = CPW / 8;                 // 8-col mma groups
    constexpr int STRW = M3 + 8;                  // W smem stride (== 8 mod 32)

    for (int e = tid; e < P.ncg; e += NTHREADS)
        scg[e] = make_float2(P.cg_val[e], __int_as_float(P.cg_pack[e]));

    float acc[L3][NC][2][4];
#pragma unroll
    for (int k = 0; k < L3; ++k)
#pragma unroll
        for (int nc = 0; nc < NC; ++nc)
#pragma unroll
            for (int r2 = 0; r2 < 2; ++r2)
#pragma unroll
                for (int q = 0; q < 4; ++q) acc[k][nc][r2][q] = 0.f;

    for (int p = 0; p < P.npaths; ++p) {
        const PathP& pp = P.path[p];
        const float* gx1 = x1 + (size_t)tile * 64 * 480 + pp.off1;
        const float* gx2 = x2 + (size_t)tile * 64 * 480 + pp.off2;
        int begs[L3 + 1];
#pragma unroll
        for (int k = 0; k <= L3; ++k) begs[k] = pp.cg_beg[k];
        const int KUV = pp.m1 * pp.m2, m2 = pp.m2, L2 = pp.L2, L1 = pp.L1;
        const int scq = (32 * L2) >> 2;   // float4 cols in strip

        for (int uv0 = 0; uv0 < KUV; uv0 += 32) {
            const int v0 = uv0 & (m2 - 1);

            // stage x1 u-row when u changes
            if (v0 == 0 && tid < 64) {
                const int u = uv0 >> pp.m2shift;
                for (int i = 0; i < L1; ++i)
                    x1row[i * 65 + tid] = gx1[tid * 480 + u * L1 + i];
            }
            // stage x2 strip [32*L2][64] (skip re-stage when it covers all of x2)
            if (m2 != 32 || uv0 == 0) {
                for (int idx = tid; idx < 64 * scq; idx += NTHREADS) {
                    int b = idx / scq, q = idx - b * scq;
                    float4 v = *(const float4*)(gx2 + b * 480 + v0 * L2 + 4 * q);
                    int c = 4 * q;
                    strip[(c + 0) * 65 + b] = v.x; strip[(c + 1) * 65 + b] = v.y;
                    strip[(c + 2) * 65 + b] = v.z; strip[(c + 3) * 65 + b] = v.w;
                }
            }
            // stage W chunk [32][M3] -> tf32
            {
                constexpr int RQ = M3 / 4;
                const float4* gw = (const float4*)(wgt + (size_t)pp.woff + (size_t)uv0 * M3);
#pragma unroll
                for (int idx = tid; idx < 32 * RQ; idx += NTHREADS) {
                    int kc = idx / RQ, q = idx - kc * RQ;
                    float4 v = gw[idx];
                    uint32_t* d = sW + kc * STRW + 4 * q;
                    d[0] = to_tf32(v.x); d[1] = to_tf32(v.y);
                    d[2] = to_tf32(v.z); d[3] = to_tf32(v.w);
                }
            }
            __syncthreads();

            // ---- P compute: (b, kc) pairs -> sA[k][b][kc] as tf32 ----
            {
                const int kc = tid & 31, bg = tid >> 5;
                const char* sbase = (const char*)strip + (size_t)(kc * L2) * 260;
#pragma unroll
                for (int it = 0; it < 8; ++it) {
                    const int b = it * 8 + bg;
                    const char* p1 = (const char*)x1row + b * 4;
                    const char* p2 = sbase + b * 4;
#pragma unroll
                    for (int k = 0; k < L3; ++k) {
                        float s = 0.f;
                        for (int e = begs[k]; e < begs[k + 1]; ++e) {
                            float2 ce = scg[e];
                            uint32_t pk = __float_as_uint(ce.y);
                            float f1 = *(const float*)(p1 + (pk & 0xffff));
                            float f2 = *(const float*)(p2 + (pk >> 16));
                            s += ce.x * f1 * f2;
                        }
                        sA[k * 2304 + b * 36 + kc] = to_tf32(s);
                    }
                }
            }
            __syncthreads();

            // ---- warp MMA: acc += A(P) * B(W) ----
#pragma unroll
            for (int ks = 0; ks < 4; ++ks) {
                uint32_t a[L3][2][4];
#pragma unroll
                for (int k = 0; k < L3; ++k)
#pragma unroll
                    for (int r2 = 0; r2 < 2; ++r2) {
                        const uint32_t* Ab = sA + k * 2304
                            + (rh * 32 + r2 * 16 + gID) * 36 + ks * 8 + tIG;
                        a[k][r2][0] = Ab[0];
                        a[k][r2][1] = Ab[8 * 36];
                        a[k][r2][2] = Ab[4];
                        a[k][r2][3] = Ab[8 * 36 + 4];
                    }
                uint32_t bb[NC][2];
#pragma unroll
                for (int nc = 0; nc < NC; ++nc) {
                    const uint32_t* Bb = sW + (ks * 8 + tIG) * STRW + cgp * CPW + nc * 8 + gID;
                    bb[nc][0] = Bb[0];
                    bb[nc][1] = Bb[4 * STRW];
                }
#pragma unroll
                for (int k = 0; k < L3; ++k)
#pragma unroll
                    for (int nc = 0; nc < NC; ++nc)
#pragma unroll
                        for (int r2 = 0; r2 < 2; ++r2)
                            mma8(acc[k][nc][r2], a[k][r2], bb[nc]);
            }
            __syncthreads();
        }
    }

    // ---- epilogue: registers -> out (mul_ir layout: col = w*L3 + k) ----
    const float coeff = P.coeff;
#pragma unroll
    for (int k = 0; k < L3; ++k)
#pragma unroll
        for (int nc = 0; nc < NC; ++nc)
#pragma unroll
            for (int r2 = 0; r2 < 2; ++r2) {
                const int wc = cgp * CPW + nc * 8 + 2 * tIG;
                const int row = tile * 64 + rh * 32 + r2 * 16 + gID;
                float* po = out + (size_t)row * 480 + OFF3;
                po[(wc + 0) * L3 + k] = coeff * acc[k][nc][r2][0];
                po[(wc + 1) * L3 + k] = coeff * acc[k][nc][r2][1];
                po += 8 * 480;
                po[(wc + 0) * L3 + k] = coeff * acc[k][nc][r2][2];
                po[(wc + 1) * L3 + k] = coeff * acc[k][nc][r2][3];
            }
}

__global__ void __launch_bounds__(NTHREADS, 2)
tp_kernel(const float* __restrict__ x1, const float* __restrict__ x2,
          const float* __restrict__ wgt, float* __restrict__ out, AllParams ap)
{
    const int tile = blockIdx.y;
    if (blockIdx.x == 0)      run_i3<128, 1, 0>  (x1, x2, wgt, out, ap.p[0], tile);
    else if (blockIdx.x == 1) run_i3<64,  3, 128>(x1, x2, wgt, out, ap.p[1], tile);
    else                      run_i3<32,  5, 320>(x1, x2, wgt, out, ap.p[2], tile);
}

// ---------------------- host: CG construction (verified R2) -----------------

typedef std::complex<double> cpx;
static double fct(int n) { double r = 1.0; for (int i = 2; i <= n; ++i) r *= i; return r; }

static void change_basis(int l, cpx q[5][5]) {
    for (int a = 0; a < 5; ++a) for (int b = 0; b < 5; ++b) q[a][b] = cpx(0, 0);
    const double s2 = 1.0 / std::sqrt(2.0);
    for (int m = -l; m < 0; ++m) {
        q[l + m][l - m] = cpx(s2, 0);
        q[l + m][l + m] = cpx(0, -s2);
    }
    q[l][l] = cpx(1, 0);
    for (int m = 1; m <= l; ++m) {
        double sg = (m & 1) ? -1.0 : 1.0;
        q[l + m][l + m] = cpx(sg * s2, 0);
        q[l + m][l - m] = cpx(0, sg * s2);
    }
    cpx ph(1, 0);
    for (int t = 0; t < l; ++t) ph *= cpx(0, -1);
    for (int a = 0; a < 2 * l + 1; ++a) for (int b = 0; b < 2 * l + 1; ++b) q[a][b] *= ph;
}

static void real_cg(int l1, int l2, int l3, float outc[5][5][5]) {
    cpx Q1[5][5], Q2[5][5], Q3[5][5];
    change_basis(l1, Q1); change_basis(l2, Q2); change_basis(l3, Q3);
    double C[5][5][5];
    memset(C, 0, sizeof(C));
    for (int m1 = -l1; m1 <= l1; ++m1)
        for (int m2 = -l2; m2 <= l2; ++m2) {
            int m3 = m1 + m2;
            if (m3 < -l3 || m3 > l3) continue;
            double pref = std::sqrt((2.0 * l3 + 1.0)
                * fct(l3 + l1 - l2) * fct(l3 - l1 + l2) * fct(l1 + l2 - l3) / fct(l1 + l2 + l3 + 1)
                * fct(l3 + m3) * fct(l3 - m3) * fct(l1 - m1) * fct(l1 + m1)
                * fct(l2 - m2) * fct(l2 + m2));
            double s = 0.0;
            for (int k = 0; k <= l1 + l2 - l3; ++k) {
                if (l1 - m1 - k < 0 || l2 + m2 - k < 0 ||
                    l3 - l2 + m1 + k < 0 || l3 - l1 - m2 + k < 0) continue;
                double d = fct(k) * fct(l1 + l2 - l3 - k) * fct(l1 - m1 - k)
                         * fct(l2 + m2 - k) * fct(l3 - l2 + m1 + k) * fct(l3 - l1 - m2 + k);
                s += ((k & 1) ? -1.0 : 1.0) / d;
            }
            C[l1 + m1][l2 + m2][l3 + m3] = pref * s;
        }
    int n1 = 2 * l1 + 1, n2 = 2 * l2 + 1, n3 = 2 * l3 + 1;
    double Rr[5][5][5], nrm = 0.0;
    for (int j = 0; j < n1; ++j)
        for (int lb = 0; lb < n2; ++lb)
            for (int nn = 0; nn < n3; ++nn) {
                cpx a(0, 0);
                for (int i = 0; i < n1; ++i)
                    for (int kk = 0; kk < n2; ++kk)
                        for (int m = 0; m < n3; ++m)
                            if (C[i][kk][m] != 0.0)
                                a += Q1[i][j] * Q2[kk][lb] * Q3[m][nn] * C[i][kk][m];
                Rr[j][lb][nn] = a.real();
                nrm += a.real() * a.real();
            }
    nrm = std::sqrt(nrm);
    for (int j = 0; j < 5; ++j) for (int lb = 0; lb < 5; ++lb) for (int nn = 0; nn < 5; ++nn)
        outc[j][lb][nn] = (j < n1 && lb < n2 && nn < n3) ? (float)(Rr[j][lb][nn] / nrm) : 0.f;
}

static void build_params(AllParams& ap) {
    memset(&ap, 0, sizeof(ap));
    const int M_[3] = {128, 64, 32}, L_[3] = {0, 1, 2}, P_[3] = {1, -1, 1},
              O_[3] = {0, 128, 320};
    long long fan[3] = {0, 0, 0};
    int woff = 0;
    for (int i1 = 0; i1 < 3; ++i1)
        for (int i2 = 0; i2 < 3; ++i2)
            for (int i3 = 0; i3 < 3; ++i3) {
                int l1 = L_[i1], l2 = L_[i2], l3 = L_[i3];
                if (P_[i1] * P_[i2] != P_[i3]) continue;
                int lo = abs(l1 - l2);
                if (l3 < lo || l3 > l1 + l2) continue;
                float C[5][5][5];
                real_cg(l1, l2, l3, C);
                Params& pr = ap.p[i3];
                PathP& pp = pr.path[pr.npaths++];
                pp.m1 = M_[i1]; pp.m2 = M_[i2];
                pp.L1 = 2 * l1 + 1; pp.L2 = 2 * l2 + 1;
                pp.off1 = O_[i1]; pp.off2 = O_[i2];
                pp.woff = woff;
                pp.m2shift = (pp.m2 == 128) ? 7 : (pp.m2 == 64) ? 6 : 5;
                int L3 = 2 * l3 + 1;
                for (int k = 0; k < L3; ++k) {
                    pp.cg_beg[k] = pr.ncg;
                    for (int i = 0; i < pp.L1; ++i)
                        for (int j = 0; j < pp.L2; ++j) {
                            float v = C[i][j][k];
                            if (fabsf(v) > 1e-12f) {
                                // pre-scaled byte offsets into [*][65] float arrays
                                pr.cg_pack[pr.ncg] = (i * 260) | ((j * 260) << 16);
                                pr.cg_val[pr.ncg] = v;
                                pr.ncg++;
                            }
                        }
                }
                pp.cg_beg[L3] = pr.ncg;
                woff += pp.m1 * pp.m2 * M_[i3];
                fan[i3] += (long long)pp.m1 * pp.m2;
            }
    for (int i3 = 0; i3 < 3; ++i3)
        ap.p[i3].coeff = std::sqrt((double)(2 * L_[i3] + 1) / (double)fan[i3]);
}

// ------------------------------ entry ---------------------------------------

extern "C" void kernel_launch(void* const* d_in, const int* in_sizes, int n_in,
                              void* d_out, int out_size) {
    AllParams ap;
    build_params(ap);
    cudaFuncSetAttribute(tp_kernel, cudaFuncAttributeMaxDynamicSharedMemorySize, SMEM_TOTAL);
    tp_kernel<<<dim3(3, 128), NTHREADS, SMEM_TOTAL>>>(
        (const float*)d_in[0], (const float*)d_in[1], (const float*)d_in[2],
        (float*)d_out, ap);
}

// round 7
// speedup vs baseline: 5.1425x; 5.1425x over previous
#include <cuda_runtime.h>
#include <cstdint>
#include <cmath>
#include <cstring>
#include <complex>
#include <cstdlib>

#define NT 256
struct TPParams { float cg[384]; float coeff[3]; int cgo[12]; int woff[12]; };

// smem: [0:1536) cg, [1536) x1row 5*65*4, [2944) sx2 192*65*4, [52864) sW, then sA
#define OX1 1536
#define OX2 2944
#define OW  52864
#define SMT 104064

__device__ __forceinline__ uint32_t to_tf32(float f){
    uint32_t r; asm("cvt.rna.tf32.f32 %0,%1;":"=r"(r):"f"(f)); return r;
}
__device__ __forceinline__ void mma8(float* d,const uint32_t* a,const uint32_t* b){
    asm volatile("mma.sync.aligned.m16n8k8.row.col.f32.tf32.tf32.f32 "
        "{%0,%1,%2,%3},{%4,%5,%6,%7},{%8,%9},{%0,%1,%2,%3};"
        :"+f"(d[0]),"+f"(d[1]),"+f"(d[2]),"+f"(d[3])
        :"r"(a[0]),"r"(a[1]),"r"(a[2]),"r"(a[3]),"r"(b[0]),"r"(b[1]));
}

template<int M3,int L3,int L1,int L2,int M1,int M2>
__device__ __forceinline__ void do_path(
    const float* __restrict__ gx1,const float* __restrict__ gx2,
    const float* __restrict__ gw,const float* __restrict__ cg,
    float* x1row,float* sx2,uint32_t* sW,uint32_t* sA,
    float (&acc)[L3][M3/32][2][4])
{
    constexpr int NC=M3/32, CPW=M3/4, STRW=M3+8, RQ=M3/4, C2q=(M2*L2)/4;
    const int tid=threadIdx.x, wid=tid>>5, lane=tid&31;
    const int cgp=wid&3, rh=wid>>2, gID=lane>>2, tIG=lane&3;

    __syncthreads();                       // prior phase fully drained
    // stage x2 block [c][b] once per path
    for(int idx=tid; idx<64*C2q; idx+=NT){
        int b=idx/C2q, q=idx-b*C2q;
        float4 v=*(const float4*)(gx2+b*480+4*q);
        float vv[4]={v.x,v.y,v.z,v.w};
#pragma unroll
        for(int e=0;e<4;++e) sx2[(4*q+e)*65+b]=vv[e];
    }
    for(int uv0=0; uv0<M1*M2; uv0+=32){
        const int v0=uv0&(M2-1);
        if(v0==0 && tid<64){
            const int u=uv0/M2;
#pragma unroll
            for(int i=0;i<L1;++i) x1row[i*65+tid]=gx1[tid*480+u*L1+i];
        }
        {   // stage W chunk [32][M3] -> tf32
            const float4* g4=(const float4*)(gw+(size_t)uv0*M3);
#pragma unroll
            for(int t=0;t<32*RQ/NT;++t){
                int idx=t*NT+tid, kc=idx/RQ, q=idx-kc*RQ;
                float4 v=g4[idx];
                uint32_t* dd=sW+kc*STRW+4*q;
                dd[0]=to_tf32(v.x); dd[1]=to_tf32(v.y);
                dd[2]=to_tf32(v.z); dd[3]=to_tf32(v.w);
            }
        }
        __syncthreads();
        {   // dense unrolled P-compute: (b,kc) -> sA[k][b][kc]
            const int kc=tid&31, bg=tid>>5;
            const float* c2=sx2+(v0+kc)*L2*65;
#pragma unroll
            for(int it=0;it<8;++it){
                const int b=it*8+bg;
                float a1[L1], a2[L2], pr[L1*L2];
#pragma unroll
                for(int i=0;i<L1;++i) a1[i]=x1row[i*65+b];
#pragma unroll
                for(int j=0;j<L2;++j) a2[j]=c2[j*65+b];
#pragma unroll
                for(int i=0;i<L1;++i)
#pragma unroll
                    for(int j=0;j<L2;++j) pr[i*L2+j]=a1[i]*a2[j];
#pragma unroll
                for(int k=0;k<L3;++k){
                    float s=0.f;
#pragma unroll
                    for(int n=0;n<L1*L2;++n) s+=cg[n*L3+k]*pr[n];
                    sA[k*2304+b*36+kc]=to_tf32(s);
                }
            }
        }
        __syncthreads();
        // warp MMA (verified R4 fragment mapping)
#pragma unroll
        for(int ks=0;ks<4;++ks){
            uint32_t a[L3][2][4];
#pragma unroll
            for(int k=0;k<L3;++k)
#pragma unroll
                for(int r2=0;r2<2;++r2){
                    const uint32_t* Ab=sA+k*2304+(rh*32+r2*16+gID)*36+ks*8+tIG;
                    a[k][r2][0]=Ab[0]; a[k][r2][1]=Ab[288];
                    a[k][r2][2]=Ab[4]; a[k][r2][3]=Ab[292];
                }
            uint32_t bb[NC][2];
#pragma unroll
            for(int nc=0;nc<NC;++nc){
                const uint32_t* Bb=sW+(ks*8+tIG)*STRW+cgp*CPW+nc*8+gID;
                bb[nc][0]=Bb[0]; bb[nc][1]=Bb[4*STRW];
            }
#pragma unroll
            for(int k=0;k<L3;++k)
#pragma unroll
                for(int nc=0;nc<NC;++nc)
#pragma unroll
                    for(int r2=0;r2<2;++r2)
                        mma8(acc[k][nc][r2],a[k][r2],bb[nc]);
        }
        __syncthreads();
    }
}

template<int M3,int L3,int OFF3>
__device__ __forceinline__ void epilogue(float (&acc)[L3][M3/32][2][4],
    float* __restrict__ out,int tile,float coeff)
{
    const int tid=threadIdx.x, wid=tid>>5, lane=tid&31;
    const int cgp=wid&3, rh=wid>>2, gID=lane>>2, tIG=lane&3;
    constexpr int NC=M3/32, CPW=M3/4;
#pragma unroll
    for(int k=0;k<L3;++k)
#pragma unroll
        for(int nc=0;nc<NC;++nc)
#pragma unroll
            for(int r2=0;r2<2;++r2){
                const int wc=cgp*CPW+nc*8+2*tIG;
                const int row=tile*64+rh*32+r2*16+gID;
                float* po=out+(size_t)row*480+OFF3;
                po[(wc+0)*L3+k]=coeff*acc[k][nc][r2][0];
                po[(wc+1)*L3+k]=coeff*acc[k][nc][r2][1];
                po+=8*480;
                po[(wc+0)*L3+k]=coeff*acc[k][nc][r2][2];
                po[(wc+1)*L3+k]=coeff*acc[k][nc][r2][3];
            }
}

__global__ void __launch_bounds__(NT,2)
tp_kernel(const float* __restrict__ x1,const float* __restrict__ x2,
          const float* __restrict__ wgt,float* __restrict__ out,
          const __grid_constant__ TPParams P)
{
    extern __shared__ char sm[];
    float* scg=(float*)sm;
    for(int e=threadIdx.x;e<384;e+=NT) scg[e]=P.cg[e];
    const int tile=blockIdx.y;
    const float* X1=x1+(size_t)tile*64*480;
    const float* X2=x2+(size_t)tile*64*480;
    float* x1row=(float*)(sm+OX1);
    float* sx2=(float*)(sm+OX2);
    const float* w=wgt;

    if(blockIdx.x==0){
        uint32_t* sW=(uint32_t*)(sm+OW);
        uint32_t* sA=(uint32_t*)(sm+OW+32*136*4);
        float acc[1][4][2][4]={};
        do_path<128,1,1,1,128,128>(X1,    X2,    w+P.woff[0],scg+P.cgo[0],x1row,sx2,sW,sA,acc);
        do_path<128,1,3,3, 64, 64>(X1+128,X2+128,w+P.woff[4],scg+P.cgo[4],x1row,sx2,sW,sA,acc);
        do_path<128,1,5,5, 32, 32>(X1+320,X2+320,w+P.woff[9],scg+P.cgo[9],x1row,sx2,sW,sA,acc);
        epilogue<128,1,0>(acc,out,tile,P.coeff[0]);
    } else if(blockIdx.x==1){
        uint32_t* sW=(uint32_t*)(sm+OW);
        uint32_t* sA=(uint32_t*)(sm+OW+32*72*4);
        float acc[3][2][2][4]={};
        do_path<64,3,1,3,128, 64>(X1,    X2+128,w+P.woff[1],scg+P.cgo[1],x1row,sx2,sW,sA,acc);
        do_path<64,3,3,1, 64,128>(X1+128,X2,    w+P.woff[3],scg+P.cgo[3],x1row,sx2,sW,sA,acc);
        do_path<64,3,3,5, 64, 32>(X1+128,X2+320,w+P.woff[6],scg+P.cgo[6],x1row,sx2,sW,sA,acc);
        do_path<64,3,5,3, 32, 64>(X1+320,X2+128,w+P.woff[8],scg+P.cgo[8],x1row,sx2,sW,sA,acc);
        epilogue<64,3,128>(acc,out,tile,P.coeff[1]);
    } else {
        uint32_t* sW=(uint32_t*)(sm+OW);
        uint32_t* sA=(uint32_t*)(sm+OW+32*40*4);
        float acc[5][1][2][4]={};
        do_path<32,5,1,5,128, 32>(X1,    X2+320,w+P.woff[2], scg+P.cgo[2], x1row,sx2,sW,sA,acc);
        do_path<32,5,3,3, 64, 64>(X1+128,X2+128,w+P.woff[5], scg+P.cgo[5], x1row,sx2,sW,sA,acc);
        do_path<32,5,5,1, 32,128>(X1+320,X2,    w+P.woff[7], scg+P.cgo[7], x1row,sx2,sW,sA,acc);
        do_path<32,5,5,5, 32, 32>(X1+320,X2+320,w+P.woff[10],scg+P.cgo[10],x1row,sx2,sW,sA,acc);
        epilogue<32,5,320>(acc,out,tile,P.coeff[2]);
    }
}

// ---------------------- host: CG construction (verified) --------------------

typedef std::complex<double> cpx;
static double fct(int n){double r=1.0;for(int i=2;i<=n;++i)r*=i;return r;}

static void change_basis(int l, cpx q[5][5]){
    for(int a=0;a<5;++a)for(int b=0;b<5;++b)q[a][b]=cpx(0,0);
    const double s2=1.0/std::sqrt(2.0);
    for(int m=-l;m<0;++m){ q[l+m][l-m]=cpx(s2,0); q[l+m][l+m]=cpx(0,-s2); }
    q[l][l]=cpx(1,0);
    for(int m=1;m<=l;++m){
        double sg=(m&1)?-1.0:1.0;
        q[l+m][l+m]=cpx(sg*s2,0); q[l+m][l-m]=cpx(0,sg*s2);
    }
    cpx ph(1,0);
    for(int t=0;t<l;++t)ph*=cpx(0,-1);
    for(int a=0;a<2*l+1;++a)for(int b=0;b<2*l+1;++b)q[a][b]*=ph;
}

static void real_cg(int l1,int l2,int l3,float outc[5][5][5]){
    cpx Q1[5][5],Q2[5][5],Q3[5][5];
    change_basis(l1,Q1); change_basis(l2,Q2); change_basis(l3,Q3);
    double C[5][5][5]; memset(C,0,sizeof(C));
    for(int m1=-l1;m1<=l1;++m1)
        for(int m2=-l2;m2<=l2;++m2){
            int m3=m1+m2;
            if(m3<-l3||m3>l3)continue;
            double pref=std::sqrt((2.0*l3+1.0)
                *fct(l3+l1-l2)*fct(l3-l1+l2)*fct(l1+l2-l3)/fct(l1+l2+l3+1)
                *fct(l3+m3)*fct(l3-m3)*fct(l1-m1)*fct(l1+m1)*fct(l2-m2)*fct(l2+m2));
            double s=0.0;
            for(int k=0;k<=l1+l2-l3;++k){
                if(l1-m1-k<0||l2+m2-k<0||l3-l2+m1+k<0||l3-l1-m2+k<0)continue;
                double d=fct(k)*fct(l1+l2-l3-k)*fct(l1-m1-k)
                        *fct(l2+m2-k)*fct(l3-l2+m1+k)*fct(l3-l1-m2+k);
                s+=((k&1)?-1.0:1.0)/d;
            }
            C[l1+m1][l2+m2][l3+m3]=pref*s;
        }
    int n1=2*l1+1,n2=2*l2+1,n3=2*l3+1;
    double Rr[5][5][5],nrm=0.0;
    for(int j=0;j<n1;++j)
        for(int lb=0;lb<n2;++lb)
            for(int nn=0;nn<n3;++nn){
                cpx a(0,0);
                for(int i=0;i<n1;++i)
                    for(int kk=0;kk<n2;++kk)
                        for(int m=0;m<n3;++m)
                            if(C[i][kk][m]!=0.0)
                                a+=Q1[i][j]*Q2[kk][lb]*Q3[m][nn]*C[i][kk][m];
                Rr[j][lb][nn]=a.real();
                nrm+=a.real()*a.real();
            }
    nrm=std::sqrt(nrm);
    for(int j=0;j<5;++j)for(int lb=0;lb<5;++lb)for(int nn=0;nn<5;++nn)
        outc[j][lb][nn]=(j<n1&&lb<n2&&nn<n3)?(float)(Rr[j][lb][nn]/nrm):0.f;
}

static void build_params(TPParams& P){
    memset(&P,0,sizeof(P));
    const int M_[3]={128,64,32}, L_[3]={0,1,2}, Pa[3]={1,-1,1};
    long long fan[3]={0,0,0};
    int woff=0, cgo=0, idx=0;
    for(int i1=0;i1<3;++i1)for(int i2=0;i2<3;++i2)for(int i3=0;i3<3;++i3){
        int l1=L_[i1],l2=L_[i2],l3=L_[i3];
        if(Pa[i1]*Pa[i2]!=Pa[i3])continue;
        if(l3<abs(l1-l2)||l3>l1+l2)continue;
        float C[5][5][5];
        real_cg(l1,l2,l3,C);
        P.woff[idx]=woff; P.cgo[idx]=cgo;
        int n1=2*l1+1,n2=2*l2+1,n3=2*l3+1;
        for(int i=0;i<n1;++i)for(int j=0;j<n2;++j)for(int k=0;k<n3;++k)
            P.cg[cgo++]=C[i][j][k];
        woff+=M_[i1]*M_[i2]*M_[i3];
        fan[i3]+=(long long)M_[i1]*M_[i2];
        ++idx;
    }
    for(int t=0;t<3;++t)
        P.coeff[t]=(float)std::sqrt((double)(2*L_[t]+1)/(double)fan[t]);
}

// ------------------------------ entry ---------------------------------------

extern "C" void kernel_launch(void* const* d_in, const int* in_sizes, int n_in,
                              void* d_out, int out_size) {
    TPParams P;
    build_params(P);
    cudaFuncSetAttribute(tp_kernel, cudaFuncAttributeMaxDynamicSharedMemorySize, SMT);
    tp_kernel<<<dim3(3,128), NT, SMT>>>(
        (const float*)d_in[0], (const float*)d_in[1], (const float*)d_in[2],
        (float*)d_out, P);
}

// round 8
// speedup vs baseline: 6.7270x; 1.3081x over previous
#include <cuda_runtime.h>
#include <cstdint>
#include <cmath>
#include <cstring>
#include <complex>
#include <cstdlib>

#define NT 256
struct TPParams { float cg[384]; float coeff[3]; int cgo[12]; int woff[12]; };

// smem: [0:1536) cg fp32, [1536) x1row 5*65*4, [2880) sx2 192*65*4=49920,
// [52800) sWp 16*(M3+8)*4, then sAh L3*64*20*4
#define OX1 1536
#define OX2 2880
#define OW  52800
#define SMT 80960

__device__ __forceinline__ uint32_t pack2(float lo, float hi){
    uint32_t r; asm("cvt.rn.f16x2.f32 %0,%1,%2;":"=r"(r):"f"(hi),"f"(lo)); return r;
}
__device__ __forceinline__ void mma16(float* d,const uint32_t* a,const uint32_t* b){
    asm volatile("mma.sync.aligned.m16n8k16.row.col.f32.f16.f16.f32 "
        "{%0,%1,%2,%3},{%4,%5,%6,%7},{%8,%9},{%0,%1,%2,%3};"
        :"+f"(d[0]),"+f"(d[1]),"+f"(d[2]),"+f"(d[3])
        :"r"(a[0]),"r"(a[1]),"r"(a[2]),"r"(a[3]),"r"(b[0]),"r"(b[1]));
}

template<int M3,int L3,int L1,int L2,int M1,int M2>
__device__ __forceinline__ void do_path(
    const float* __restrict__ gx1,const float* __restrict__ gx2,
    const float* __restrict__ gw,const float* __restrict__ cg,
    float* x1row,float* sx2,uint32_t* sWp,uint32_t* sAh,
    float (&acc)[L3][M3/32][2][4])
{
    constexpr int NC=M3/32, CPW=M3/4, WS=M3+8, C2q=(M2*L2)/4;
    const int tid=threadIdx.x, wid=tid>>5, lane=tid&31;
    const int cgp=wid&3, rh=wid>>2, gID=lane>>2, tIG=lane&3;

    __syncthreads();                      // prior phase fully drained
    // stage x2 block [c][b] once per path (fp32)
    for(int idx=tid; idx<64*C2q; idx+=NT){
        int b=idx/C2q, q=idx-b*C2q;
        float4 v=*(const float4*)(gx2+b*480+4*q);
        float vv[4]={v.x,v.y,v.z,v.w};
#pragma unroll
        for(int e=0;e<4;++e) sx2[(4*q+e)*65+b]=vv[e];
    }
    for(int uv0=0; uv0<M1*M2; uv0+=32){
        const int v0=uv0&(M2-1);
        if(v0==0 && tid<64){
            const int u=uv0/M2;
#pragma unroll
            for(int i=0;i<L1;++i) x1row[i*65+tid]=gx1[tid*480+u*L1+i];
        }
        // stage W as k-pair half2: sWp[p][w], p=0..15
        for(int idx=tid; idx<16*(M3/4); idx+=NT){
            int p=idx/(M3/4), wq=idx-p*(M3/4);
            float4 lo=*(const float4*)(gw+(size_t)(uv0+2*p)*M3+4*wq);
            float4 hi=*(const float4*)(gw+(size_t)(uv0+2*p+1)*M3+4*wq);
            uint4 d;
            d.x=pack2(lo.x,hi.x); d.y=pack2(lo.y,hi.y);
            d.z=pack2(lo.z,hi.z); d.w=pack2(lo.w,hi.w);
            *(uint4*)(sWp+p*WS+4*wq)=d;
        }
        __syncthreads();
        // P compute: (b, kc-pair q) -> sAh[k][b][q] as half2
        {
            const int q=tid&15, bg=tid>>4;
            const float* c2a=sx2+(v0+2*q)*L2*65;
            const float* c2b=c2a+L2*65;
#pragma unroll
            for(int it=0;it<4;++it){
                const int b=it*16+bg;
                float a1[L1];
#pragma unroll
                for(int i=0;i<L1;++i) a1[i]=x1row[i*65+b];
                float pa[L3], pb[L3];
#pragma unroll
                for(int k=0;k<L3;++k){ pa[k]=0.f; pb[k]=0.f; }
#pragma unroll
                for(int i=0;i<L1;++i)
#pragma unroll
                    for(int j=0;j<L2;++j){
                        float xa=a1[i]*c2a[j*65+b];
                        float xb=a1[i]*c2b[j*65+b];
#pragma unroll
                        for(int k=0;k<L3;++k){
                            float c=cg[(i*L2+j)*L3+k];
                            pa[k]+=c*xa; pb[k]+=c*xb;
                        }
                    }
#pragma unroll
                for(int k=0;k<L3;++k)
                    sAh[k*1280+b*20+q]=pack2(pa[k],pb[k]);
            }
        }
        __syncthreads();
        // warp MMA fp16 k16
#pragma unroll
        for(int ks=0;ks<2;++ks){
            uint32_t a[L3][2][4];
#pragma unroll
            for(int k=0;k<L3;++k)
#pragma unroll
                for(int r2=0;r2<2;++r2){
                    const uint32_t* Ab=sAh+k*1280+(rh*32+r2*16+gID)*20+ks*8+tIG;
                    a[k][r2][0]=Ab[0];   a[k][r2][1]=Ab[160];
                    a[k][r2][2]=Ab[4];   a[k][r2][3]=Ab[164];
                }
            uint32_t bb[NC][2];
#pragma unroll
            for(int nc=0;nc<NC;++nc){
                const uint32_t* Bb=sWp+(ks*8+tIG)*WS+cgp*CPW+nc*8+gID;
                bb[nc][0]=Bb[0]; bb[nc][1]=Bb[4*WS];
            }
#pragma unroll
            for(int k=0;k<L3;++k)
#pragma unroll
                for(int nc=0;nc<NC;++nc)
#pragma unroll
                    for(int r2=0;r2<2;++r2)
                        mma16(acc[k][nc][r2],a[k][r2],bb[nc]);
        }
        __syncthreads();
    }
}

template<int M3,int L3,int OFF3>
__device__ __forceinline__ void epilogue(float (&acc)[L3][M3/32][2][4],
    float* __restrict__ out,int tile,float coeff)
{
    const int tid=threadIdx.x, wid=tid>>5, lane=tid&31;
    const int cgp=wid&3, rh=wid>>2, gID=lane>>2, tIG=lane&3;
    constexpr int NC=M3/32, CPW=M3/4;
#pragma unroll
    for(int k=0;k<L3;++k)
#pragma unroll
        for(int nc=0;nc<NC;++nc)
#pragma unroll
            for(int r2=0;r2<2;++r2){
                const int wc=cgp*CPW+nc*8+2*tIG;
                const int row=tile*64+rh*32+r2*16+gID;
                float* po=out+(size_t)row*480+OFF3;
                po[(wc+0)*L3+k]=coeff*acc[k][nc][r2][0];
                po[(wc+1)*L3+k]=coeff*acc[k][nc][r2][1];
                po+=8*480;
                po[(wc+0)*L3+k]=coeff*acc[k][nc][r2][2];
                po[(wc+1)*L3+k]=coeff*acc[k][nc][r2][3];
            }
}

__global__ void __launch_bounds__(NT,2)
tp_kernel(const float* __restrict__ x1,const float* __restrict__ x2,
          const float* __restrict__ wgt,float* __restrict__ out,
          const __grid_constant__ TPParams P)
{
    extern __shared__ char sm[];
    float* scg=(float*)sm;
    for(int e=threadIdx.x;e<384;e+=NT) scg[e]=P.cg[e];
    const int tile=blockIdx.y;
    const float* X1=x1+(size_t)tile*64*480;
    const float* X2=x2+(size_t)tile*64*480;
    float* x1row=(float*)(sm+OX1);
    float* sx2=(float*)(sm+OX2);
    uint32_t* sWp=(uint32_t*)(sm+OW);
    const float* w=wgt;

    if(blockIdx.x==0){
        uint32_t* sAh=(uint32_t*)(sm+OW+16*136*4);
        float acc[1][4][2][4]={};
        do_path<128,1,1,1,128,128>(X1,    X2,    w+P.woff[0],scg+P.cgo[0],x1row,sx2,sWp,sAh,acc);
        do_path<128,1,3,3, 64, 64>(X1+128,X2+128,w+P.woff[4],scg+P.cgo[4],x1row,sx2,sWp,sAh,acc);
        do_path<128,1,5,5, 32, 32>(X1+320,X2+320,w+P.woff[9],scg+P.cgo[9],x1row,sx2,sWp,sAh,acc);
        epilogue<128,1,0>(acc,out,tile,P.coeff[0]);
    } else if(blockIdx.x==1){
        uint32_t* sAh=(uint32_t*)(sm+OW+16*72*4);
        float acc[3][2][2][4]={};
        do_path<64,3,1,3,128, 64>(X1,    X2+128,w+P.woff[1],scg+P.cgo[1],x1row,sx2,sWp,sAh,acc);
        do_path<64,3,3,1, 64,128>(X1+128,X2,    w+P.woff[3],scg+P.cgo[3],x1row,sx2,sWp,sAh,acc);
        do_path<64,3,3,5, 64, 32>(X1+128,X2+320,w+P.woff[6],scg+P.cgo[6],x1row,sx2,sWp,sAh,acc);
        do_path<64,3,5,3, 32, 64>(X1+320,X2+128,w+P.woff[8],scg+P.cgo[8],x1row,sx2,sWp,sAh,acc);
        epilogue<64,3,128>(acc,out,tile,P.coeff[1]);
    } else {
        uint32_t* sAh=(uint32_t*)(sm+OW+16*40*4);
        float acc[5][1][2][4]={};
        do_path<32,5,1,5,128, 32>(X1,    X2+320,w+P.woff[2], scg+P.cgo[2], x1row,sx2,sWp,sAh,acc);
        do_path<32,5,3,3, 64, 64>(X1+128,X2+128,w+P.woff[5], scg+P.cgo[5], x1row,sx2,sWp,sAh,acc);
        do_path<32,5,5,1, 32,128>(X1+320,X2,    w+P.woff[7], scg+P.cgo[7], x1row,sx2,sWp,sAh,acc);
        do_path<32,5,5,5, 32, 32>(X1+320,X2+320,w+P.woff[10],scg+P.cgo[10],x1row,sx2,sWp,sAh,acc);
        epilogue<32,5,320>(acc,out,tile,P.coeff[2]);
    }
}

// ---------------------- host: CG construction (verified) --------------------

typedef std::complex<double> cpx;
static double fct(int n){double r=1.0;for(int i=2;i<=n;++i)r*=i;return r;}

static void change_basis(int l, cpx q[5][5]){
    for(int a=0;a<5;++a)for(int b=0;b<5;++b)q[a][b]=cpx(0,0);
    const double s2=1.0/std::sqrt(2.0);
    for(int m=-l;m<0;++m){ q[l+m][l-m]=cpx(s2,0); q[l+m][l+m]=cpx(0,-s2); }
    q[l][l]=cpx(1,0);
    for(int m=1;m<=l;++m){
        double sg=(m&1)?-1.0:1.0;
        q[l+m][l+m]=cpx(sg*s2,0); q[l+m][l-m]=cpx(0,sg*s2);
    }
    cpx ph(1,0);
    for(int t=0;t<l;++t)ph*=cpx(0,-1);
    for(int a=0;a<2*l+1;++a)for(int b=0;b<2*l+1;++b)q[a][b]*=ph;
}

static void real_cg(int l1,int l2,int l3,float outc[5][5][5]){
    cpx Q1[5][5],Q2[5][5],Q3[5][5];
    change_basis(l1,Q1); change_basis(l2,Q2); change_basis(l3,Q3);
    double C[5][5][5]; memset(C,0,sizeof(C));
    for(int m1=-l1;m1<=l1;++m1)
        for(int m2=-l2;m2<=l2;++m2){
            int m3=m1+m2;
            if(m3<-l3||m3>l3)continue;
            double pref=std::sqrt((2.0*l3+1.0)
                *fct(l3+l1-l2)*fct(l3-l1+l2)*fct(l1+l2-l3)/fct(l1+l2+l3+1)
                *fct(l3+m3)*fct(l3-m3)*fct(l1-m1)*fct(l1+m1)*fct(l2-m2)*fct(l2+m2));
            double s=0.0;
            for(int k=0;k<=l1+l2-l3;++k){
                if(l1-m1-k<0||l2+m2-k<0||l3-l2+m1+k<0||l3-l1-m2+k<0)continue;
                double d=fct(k)*fct(l1+l2-l3-k)*fct(l1-m1-k)
                        *fct(l2+m2-k)*fct(l3-l2+m1+k)*fct(l3-l1-m2+k);
                s+=((k&1)?-1.0:1.0)/d;
            }
            C[l1+m1][l2+m2][l3+m3]=pref*s;
        }
    int n1=2*l1+1,n2=2*l2+1,n3=2*l3+1;
    double Rr[5][5][5],nrm=0.0;
    for(int j=0;j<n1;++j)
        for(int lb=0;lb<n2;++lb)
            for(int nn=0;nn<n3;++nn){
                cpx a(0,0);
                for(int i=0;i<n1;++i)
                    for(int kk=0;kk<n2;++kk)
                        for(int m=0;m<n3;++m)
                            if(C[i][kk][m]!=0.0)
                                a+=Q1[i][j]*Q2[kk][lb]*Q3[m][nn]*C[i][kk][m];
                Rr[j][lb][nn]=a.real();
                nrm+=a.real()*a.real();
            }
    nrm=std::sqrt(nrm);
    for(int j=0;j<5;++j)for(int lb=0;lb<5;++lb)for(int nn=0;nn<5;++nn)
        outc[j][lb][nn]=(j<n1&&lb<n2&&nn<n3)?(float)(Rr[j][lb][nn]/nrm):0.f;
}

static void build_params(TPParams& P){
    memset(&P,0,sizeof(P));
    const int M_[3]={128,64,32}, L_[3]={0,1,2}, Pa[3]={1,-1,1};
    long long fan[3]={0,0,0};
    int woff=0, cgo=0, idx=0;
    for(int i1=0;i1<3;++i1)for(int i2=0;i2<3;++i2)for(int i3=0;i3<3;++i3){
        int l1=L_[i1],l2=L_[i2],l3=L_[i3];
        if(Pa[i1]*Pa[i2]!=Pa[i3])continue;
        if(l3<abs(l1-l2)||l3>l1+l2)continue;
        float C[5][5][5];
        real_cg(l1,l2,l3,C);
        P.woff[idx]=woff; P.cgo[idx]=cgo;
        int n1=2*l1+1,n2=2*l2+1,n3=2*l3+1;
        for(int i=0;i<n1;++i)for(int j=0;j<n2;++j)for(int k=0;k<n3;++k)
            P.cg[cgo++]=C[i][j][k];
        woff+=M_[i1]*M_[i2]*M_[i3];
        fan[i3]+=(long long)M_[i1]*M_[i2];
        ++idx;
    }
    for(int t=0;t<3;++t)
        P.coeff[t]=(float)std::sqrt((double)(2*L_[t]+1)/(double)fan[t]);
}

// ------------------------------ entry ---------------------------------------

extern "C" void kernel_launch(void* const* d_in, const int* in_sizes, int n_in,
                              void* d_out, int out_size) {
    TPParams P;
    build_params(P);
    cudaFuncSetAttribute(tp_kernel, cudaFuncAttributeMaxDynamicSharedMemorySize, SMT);
    tp_kernel<<<dim3(3,128), NT, SMT>>>(
        (const float*)d_in[0], (const float*)d_in[1], (const float*)d_in[2],
        (float*)d_out, P);
}